// round 2
// baseline (speedup 1.0000x reference)
#include <cuda_runtime.h>
#include <cuda_bf16.h>

// PostProcessor: fused softmax(81) + rotated-box decode for N=200000 rows.
// Layout (all float32, row-major):
//   class_logits   : [N, 81]
//   box_regression : [N, 405]   (= [N, 81, 5] flattened)
//   proposal_boxes : [N, 5]     (cx, cy, w, h, angle)
//   out            : [N, 486]   (= [softmax(81) | decoded(405)])
//
// Strategy: one warp per row. Shuffle-based softmax reduction (no smem, no
// block sync). Decode is elementwise with broadcast per-row params. Purely
// HBM-bound (~782 MB total traffic).

#define PP_N 200000
#define PP_C 81
#define PP_REG 405           // C*5
#define PP_OUT 486           // C + C*5

__global__ __launch_bounds__(256, 8)
void PostProcessor_54374285967910_kernel(
    const float* __restrict__ logits,
    const float* __restrict__ reg,
    const float* __restrict__ boxes,
    float* __restrict__ out)
{
    const int gwarp = (int)((blockIdx.x * blockDim.x + threadIdx.x) >> 5);
    const int lane  = (int)(threadIdx.x & 31);
    if (gwarp >= PP_N) return;

    const float* __restrict__ lrow = logits + (size_t)gwarp * PP_C;
    const float* __restrict__ rrow = reg    + (size_t)gwarp * PP_REG;
    float* __restrict__       orow = out    + (size_t)gwarp * PP_OUT;

    // ---------------- softmax over 81 logits ----------------
    // lanes cover indices {lane, lane+32, lane+64 (lane<17)}
    const float x0 = lrow[lane];
    const float x1 = lrow[lane + 32];
    const float x2 = (lane < 17) ? lrow[lane + 64] : -3.402823466e38f;

    float m = fmaxf(fmaxf(x0, x1), x2);
    #pragma unroll
    for (int o = 16; o > 0; o >>= 1)
        m = fmaxf(m, __shfl_xor_sync(0xffffffffu, m, o));

    const float e0 = expf(x0 - m);
    const float e1 = expf(x1 - m);
    const float e2 = (lane < 17) ? expf(x2 - m) : 0.0f;

    float s = e0 + e1 + e2;
    #pragma unroll
    for (int o = 16; o > 0; o >>= 1)
        s += __shfl_xor_sync(0xffffffffu, s, o);

    const float inv = 1.0f / s;
    orow[lane]      = e0 * inv;
    orow[lane + 32] = e1 * inv;
    if (lane < 17)
        orow[lane + 64] = e2 * inv;

    // ---------------- per-row proposal params (uniform broadcast loads) ----
    const float cx = boxes[(size_t)gwarp * 5 + 0];
    const float cy = boxes[(size_t)gwarp * 5 + 1];
    const float bw = boxes[(size_t)gwarp * 5 + 2];
    const float bh = boxes[(size_t)gwarp * 5 + 3];
    const float ba = boxes[(size_t)gwarp * 5 + 4];

    const float CLIP    = 4.135166556742356f;   // log(1000/16)
    const float RAD2DEG = 57.29577951308232f;   // 180/pi

    // ---------------- decode 405 regression values ----------------
    // component c = i % 5:
    //   0: clip(dx/10 * w + cx, [0, 1023])
    //   1: clip(dy/10 * h + cy, [0, 1023])
    //   2: exp(min(dw/5, CLIP)) * w
    //   3: exp(min(dh/5, CLIP)) * h
    //   4: da * 180/pi + angle
    #pragma unroll 4
    for (int i = lane; i < PP_REG; i += 32) {
        const float v = rrow[i];
        const int   c = i % 5;
        float r;
        if (c == 0) {
            r = fminf(fmaxf(fmaf(v * 0.1f, bw, cx), 0.0f), 1023.0f);
        } else if (c == 1) {
            r = fminf(fmaxf(fmaf(v * 0.1f, bh, cy), 0.0f), 1023.0f);
        } else if (c == 2) {
            r = expf(fminf(v * 0.2f, CLIP)) * bw;
        } else if (c == 3) {
            r = expf(fminf(v * 0.2f, CLIP)) * bh;
        } else {
            r = fmaf(v, RAD2DEG, ba);
        }
        orow[PP_C + i] = r;
    }
}

extern "C" void kernel_launch(void* const* d_in, const int* in_sizes, int n_in,
                              void* d_out, int out_size)
{
    const float* logits = (const float*)d_in[0];   // [N, 81]
    const float* reg    = (const float*)d_in[1];   // [N, 405]
    const float* boxes  = (const float*)d_in[2];   // [N, 5]
    float*       out    = (float*)d_out;           // [N, 486]

    // one warp per row, 256 threads (8 warps) per block
    const int threads = 256;
    const int rows_per_block = threads / 32;
    const int blocks = (PP_N + rows_per_block - 1) / rows_per_block;  // 25000
    PostProcessor_54374285967910_kernel<<<blocks, threads>>>(logits, reg, boxes, out);
}

// round 3
// speedup vs baseline: 1.5913x; 1.5913x over previous
#include <cuda_runtime.h>
#include <cuda_bf16.h>

// PostProcessor: fused softmax(81) + rotated-box decode, N=200000 rows.
//   class_logits   : [N, 81]   f32
//   box_regression : [N, 405]  f32  (= [N, 81, 5])
//   proposal_boxes : [N, 5]    f32  (cx, cy, w, h, angle)
//   out            : [N, 486]  f32  (= [softmax(81) | decoded(405)])
//
// R2 redesign: warp-per-row, ANCHOR-based decode (lane owns 5 consecutive
// floats -> no %5, no predicated 5-way chain), __expf fast intrinsic,
// all loads hoisted for MLP. Goal: convert issue-bound (69% issue, 36% DRAM)
// into memory-bound.

#define PP_N 200000
#define PP_C 81
#define PP_A 81              // anchors per row
#define PP_OUT 486

__global__ __launch_bounds__(256, 8)
void PostProcessor_54374285967910_kernel(
    const float* __restrict__ logits,
    const float* __restrict__ reg,
    const float* __restrict__ boxes,
    float* __restrict__ out)
{
    const int gwarp = (int)((blockIdx.x * blockDim.x + threadIdx.x) >> 5);
    const int lane  = (int)(threadIdx.x & 31);
    if (gwarp >= PP_N) return;

    const float* __restrict__ lrow = logits + (size_t)gwarp * PP_C;
    const float* __restrict__ rrow = reg    + (size_t)gwarp * (PP_A * 5);
    float* __restrict__       orow = out    + (size_t)gwarp * PP_OUT;

    // ---- per-row proposal params (issue early; mostly L2/L1 resident) ----
    const float cx = boxes[(size_t)gwarp * 5 + 0];
    const float cy = boxes[(size_t)gwarp * 5 + 1];
    const float bw = boxes[(size_t)gwarp * 5 + 2];
    const float bh = boxes[(size_t)gwarp * 5 + 3];
    const float ba = boxes[(size_t)gwarp * 5 + 4];

    // ---- softmax loads ----
    const float x0 = lrow[lane];
    const float x1 = lrow[lane + 32];
    const bool  t2 = (lane < 17);
    const float x2 = t2 ? lrow[lane + 64] : -3.402823466e38f;

    // ---- decode loads: hoist all 15 (10 + 5 predicated) scalar loads ----
    // lane owns anchors {lane, lane+32, lane+64(lane<17)}, 5 floats each.
    const float* p0 = rrow + lane * 5;
    const float* p1 = rrow + (lane + 32) * 5;
    const float* p2 = rrow + (lane + 64) * 5;
    float a0[5], a1[5], a2[5];
    #pragma unroll
    for (int j = 0; j < 5; ++j) a0[j] = p0[j];
    #pragma unroll
    for (int j = 0; j < 5; ++j) a1[j] = p1[j];
    if (t2) {
        #pragma unroll
        for (int j = 0; j < 5; ++j) a2[j] = p2[j];
    }

    // ---- softmax over 81 logits (shuffle reductions) ----
    float m = fmaxf(fmaxf(x0, x1), x2);
    #pragma unroll
    for (int o = 16; o > 0; o >>= 1)
        m = fmaxf(m, __shfl_xor_sync(0xffffffffu, m, o));

    const float e0 = __expf(x0 - m);
    const float e1 = __expf(x1 - m);
    const float e2 = t2 ? __expf(x2 - m) : 0.0f;

    float s = e0 + e1 + e2;
    #pragma unroll
    for (int o = 16; o > 0; o >>= 1)
        s += __shfl_xor_sync(0xffffffffu, s, o);

    const float inv = __fdividef(1.0f, s);
    orow[lane]      = e0 * inv;
    orow[lane + 32] = e1 * inv;
    if (t2)
        orow[lane + 64] = e2 * inv;

    // ---- decode: straight-line per-component code, no %5, no selects ----
    const float CLIP    = 4.135166556742356f;   // log(1000/16)
    const float RAD2DEG = 57.29577951308232f;   // 180/pi

    float* q0 = orow + PP_C + lane * 5;
    q0[0] = fminf(fmaxf(fmaf(a0[0] * 0.1f, bw, cx), 0.0f), 1023.0f);
    q0[1] = fminf(fmaxf(fmaf(a0[1] * 0.1f, bh, cy), 0.0f), 1023.0f);
    q0[2] = __expf(fminf(a0[2] * 0.2f, CLIP)) * bw;
    q0[3] = __expf(fminf(a0[3] * 0.2f, CLIP)) * bh;
    q0[4] = fmaf(a0[4], RAD2DEG, ba);

    float* q1 = orow + PP_C + (lane + 32) * 5;
    q1[0] = fminf(fmaxf(fmaf(a1[0] * 0.1f, bw, cx), 0.0f), 1023.0f);
    q1[1] = fminf(fmaxf(fmaf(a1[1] * 0.1f, bh, cy), 0.0f), 1023.0f);
    q1[2] = __expf(fminf(a1[2] * 0.2f, CLIP)) * bw;
    q1[3] = __expf(fminf(a1[3] * 0.2f, CLIP)) * bh;
    q1[4] = fmaf(a1[4], RAD2DEG, ba);

    if (t2) {
        float* q2 = orow + PP_C + (lane + 64) * 5;
        q2[0] = fminf(fmaxf(fmaf(a2[0] * 0.1f, bw, cx), 0.0f), 1023.0f);
        q2[1] = fminf(fmaxf(fmaf(a2[1] * 0.1f, bh, cy), 0.0f), 1023.0f);
        q2[2] = __expf(fminf(a2[2] * 0.2f, CLIP)) * bw;
        q2[3] = __expf(fminf(a2[3] * 0.2f, CLIP)) * bh;
        q2[4] = fmaf(a2[4], RAD2DEG, ba);
    }
}

extern "C" void kernel_launch(void* const* d_in, const int* in_sizes, int n_in,
                              void* d_out, int out_size)
{
    const float* logits = (const float*)d_in[0];   // [N, 81]
    const float* reg    = (const float*)d_in[1];   // [N, 405]
    const float* boxes  = (const float*)d_in[2];   // [N, 5]
    float*       out    = (float*)d_out;           // [N, 486]

    const int threads = 256;                        // 8 warps = 8 rows/block
    const int blocks  = (PP_N + 7) / 8;             // 25000
    PostProcessor_54374285967910_kernel<<<blocks, threads>>>(logits, reg, boxes, out);
}

// round 4
// speedup vs baseline: 1.8316x; 1.1510x over previous
#include <cuda_runtime.h>
#include <cuda_bf16.h>

// PostProcessor: fused softmax(81) + rotated-box decode, N=200000 rows.
//   class_logits   : [N, 81]   f32
//   box_regression : [N, 405]  f32  (= [N, 81, 5])
//   proposal_boxes : [N, 5]    f32  (cx, cy, w, h, angle)
//   out            : [N, 486]  f32  (= [softmax(81) | decoded(405)])
//
// R3: SMEM-staged. 8 rows per block. All GMEM traffic is coalesced float4
// (block regions are exactly float4-aligned/sized: 162/810/972 float4).
// The stride-5 anchor access pattern moves to SMEM where lane*5 mod 32 is a
// permutation -> conflict-free. Fixes the 5x L1tex wavefront amplification
// that capped R2 at DRAM=57%.

#define PP_N    200000
#define PP_RPB  8                  // rows per block
#define PP_L4   162                // 8*81/4  logits float4 per block
#define PP_R4   810                // 8*405/4 reg float4 per block
#define PP_O4   972                // 8*486/4 out float4 per block

__global__ __launch_bounds__(256)
void PostProcessor_54374285967910_kernel(
    const float* __restrict__ logits,
    const float* __restrict__ reg,
    const float* __restrict__ boxes,
    float* __restrict__ out)
{
    __shared__ float s_log[PP_RPB * 81];    //  648 f
    __shared__ float s_reg[PP_RPB * 405];   // 3240 f
    __shared__ float s_out[PP_RPB * 486];   // 3888 f

    const int tid  = (int)threadIdx.x;
    const int bid  = (int)blockIdx.x;
    const int warp = tid >> 5;
    const int lane = tid & 31;

    // ---------------- stage inputs: coalesced float4 ----------------
    {
        const float4* __restrict__ gl = (const float4*)(logits + (size_t)bid * (PP_RPB * 81));
        if (tid < PP_L4) ((float4*)s_log)[tid] = gl[tid];

        const float4* __restrict__ gr = (const float4*)(reg + (size_t)bid * (PP_RPB * 405));
        #pragma unroll
        for (int k = 0; k < 4; ++k) {
            const int i = tid + 256 * k;
            if (i < PP_R4) ((float4*)s_reg)[i] = gr[i];
        }
    }

    // per-row proposal params (scalar broadcast loads, no staging needed)
    const int row = bid * PP_RPB + warp;
    const float cx = boxes[(size_t)row * 5 + 0];
    const float cy = boxes[(size_t)row * 5 + 1];
    const float bw = boxes[(size_t)row * 5 + 2];
    const float bh = boxes[(size_t)row * 5 + 3];
    const float ba = boxes[(size_t)row * 5 + 4];

    __syncthreads();

    // ---------------- compute: warp w owns row w ----------------
    const float* __restrict__ lrow = s_log + warp * 81;
    const float* __restrict__ rrow = s_reg + warp * 405;
    float* __restrict__       orow = s_out + warp * 486;

    // softmax over 81 logits (lanes cover {lane, lane+32, lane+64<17})
    const bool  t2 = (lane < 17);
    const float x0 = lrow[lane];
    const float x1 = lrow[lane + 32];
    const float x2 = t2 ? lrow[lane + 64] : -3.402823466e38f;

    float m = fmaxf(fmaxf(x0, x1), x2);
    #pragma unroll
    for (int o = 16; o > 0; o >>= 1)
        m = fmaxf(m, __shfl_xor_sync(0xffffffffu, m, o));

    const float e0 = __expf(x0 - m);
    const float e1 = __expf(x1 - m);
    const float e2 = t2 ? __expf(x2 - m) : 0.0f;

    float s = e0 + e1 + e2;
    #pragma unroll
    for (int o = 16; o > 0; o >>= 1)
        s += __shfl_xor_sync(0xffffffffu, s, o);

    const float inv = __fdividef(1.0f, s);
    orow[lane]      = e0 * inv;
    orow[lane + 32] = e1 * inv;
    if (t2) orow[lane + 64] = e2 * inv;

    // decode: lane owns anchors {lane, lane+32, lane+64(<17)}, 5 floats each
    const float CLIP    = 4.135166556742356f;   // log(1000/16)
    const float RAD2DEG = 57.29577951308232f;   // 180/pi

    #pragma unroll
    for (int g = 0; g < 3; ++g) {
        const int anchor = lane + 32 * g;
        if (g == 2 && !t2) break;
        const float* p = rrow + anchor * 5;
        float a0 = p[0], a1 = p[1], a2 = p[2], a3 = p[3], a4 = p[4];
        float* q = orow + 81 + anchor * 5;
        q[0] = fminf(fmaxf(fmaf(a0 * 0.1f, bw, cx), 0.0f), 1023.0f);
        q[1] = fminf(fmaxf(fmaf(a1 * 0.1f, bh, cy), 0.0f), 1023.0f);
        q[2] = __expf(fminf(a2 * 0.2f, CLIP)) * bw;
        q[3] = __expf(fminf(a3 * 0.2f, CLIP)) * bh;
        q[4] = fmaf(a4, RAD2DEG, ba);
    }

    __syncthreads();

    // ---------------- drain output: coalesced float4 ----------------
    {
        float4* __restrict__ go = (float4*)(out + (size_t)bid * (PP_RPB * 486));
        #pragma unroll
        for (int k = 0; k < 4; ++k) {
            const int i = tid + 256 * k;
            if (i < PP_O4) go[i] = ((const float4*)s_out)[i];
        }
    }
}

extern "C" void kernel_launch(void* const* d_in, const int* in_sizes, int n_in,
                              void* d_out, int out_size)
{
    const float* logits = (const float*)d_in[0];   // [N, 81]
    const float* reg    = (const float*)d_in[1];   // [N, 405]
    const float* boxes  = (const float*)d_in[2];   // [N, 5]
    float*       out    = (float*)d_out;           // [N, 486]

    const int blocks = PP_N / PP_RPB;              // 25000, exact
    PostProcessor_54374285967910_kernel<<<blocks, 256>>>(logits, reg, boxes, out);
}

// round 5
// speedup vs baseline: 2.2341x; 1.2197x over previous
#include <cuda_runtime.h>
#include <cuda_bf16.h>
#include <cstdint>

// PostProcessor: fused softmax(81) + rotated-box decode, N=200000 rows.
//   class_logits   : [N, 81]   f32
//   box_regression : [N, 405]  f32  (= [N, 81, 5])
//   proposal_boxes : [N, 5]    f32  (cx, cy, w, h, angle)
//   out            : [N, 486]  f32  (= [softmax(81) | decoded(405)])
//
// R4: bulk-copy (UBLKCP) staged. One elected thread per block issues
// cp.async.bulk GMEM->SMEM for logits+reg (mbarrier complete_tx), warps
// compute from SMEM (anchor layout is conflict-free there), then one
// cp.async.bulk SMEM->GMEM drains the whole 15552B output block.
// Removes ~90% of SMSP-issued memory instructions (R3 was L1/issue
// throttled at DRAM=67.8%).

#define PP_N    200000
#define PP_RPB  8
#define LOG_B   (PP_RPB * 81 * 4)    //  2592 bytes, 16B-aligned per block
#define REG_B   (PP_RPB * 405 * 4)   // 12960 bytes
#define OUT_B   (PP_RPB * 486 * 4)   // 15552 bytes

__device__ __forceinline__ uint32_t smem_u32(const void* p) {
    return (uint32_t)__cvta_generic_to_shared(p);
}

__global__ __launch_bounds__(256)
void PostProcessor_54374285967910_kernel(
    const float* __restrict__ logits,
    const float* __restrict__ reg,
    const float* __restrict__ boxes,
    float* __restrict__ out)
{
    __shared__ alignas(16) float s_log[PP_RPB * 81];    //  648 f
    __shared__ alignas(16) float s_reg[PP_RPB * 405];   // 3240 f
    __shared__ alignas(16) float s_out[PP_RPB * 486];   // 3888 f
    __shared__ alignas(8)  uint64_t s_mbar;

    const int tid  = (int)threadIdx.x;
    const int bid  = (int)blockIdx.x;
    const int warp = tid >> 5;
    const int lane = tid & 31;

    const uint32_t mb = smem_u32(&s_mbar);

    if (tid == 0) {
        asm volatile("mbarrier.init.shared::cta.b64 [%0], 1;" :: "r"(mb) : "memory");
    }
    __syncthreads();   // mbarrier init visible to all threads before anyone waits

    if (tid == 0) {
        asm volatile("mbarrier.arrive.expect_tx.shared::cta.b64 _, [%0], %1;"
                     :: "r"(mb), "r"((uint32_t)(LOG_B + REG_B)) : "memory");
        asm volatile(
            "cp.async.bulk.shared::cta.global.mbarrier::complete_tx::bytes [%0], [%1], %2, [%3];"
            :: "r"(smem_u32(s_log)),
               "l"(logits + (size_t)bid * (PP_RPB * 81)),
               "r"((uint32_t)LOG_B), "r"(mb) : "memory");
        asm volatile(
            "cp.async.bulk.shared::cta.global.mbarrier::complete_tx::bytes [%0], [%1], %2, [%3];"
            :: "r"(smem_u32(s_reg)),
               "l"(reg + (size_t)bid * (PP_RPB * 405)),
               "r"((uint32_t)REG_B), "r"(mb) : "memory");
    }

    // ---- per-row proposal params: load while bulk copies are in flight ----
    const int row = bid * PP_RPB + warp;
    const float cx = boxes[(size_t)row * 5 + 0];
    const float cy = boxes[(size_t)row * 5 + 1];
    const float bw = boxes[(size_t)row * 5 + 2];
    const float bh = boxes[(size_t)row * 5 + 3];
    const float ba = boxes[(size_t)row * 5 + 4];

    // ---- wait for bulk loads (phase parity 0, acquire) ----
    {
        uint32_t done;
        asm volatile(
            "{\n\t.reg .pred p;\n\t"
            "mbarrier.try_wait.parity.acquire.cta.shared::cta.b64 p, [%1], 0;\n\t"
            "selp.b32 %0, 1, 0, p;\n\t}"
            : "=r"(done) : "r"(mb) : "memory");
        if (!done) {
            asm volatile(
                "{\n\t.reg .pred P1;\n\t"
                "WAIT_LOOP_%=:\n\t"
                "mbarrier.try_wait.parity.acquire.cta.shared::cta.b64 P1, [%0], 0, 0x989680;\n\t"
                "@P1 bra.uni WAIT_DONE_%=;\n\t"
                "bra.uni WAIT_LOOP_%=;\n\t"
                "WAIT_DONE_%=:\n\t}"
                :: "r"(mb) : "memory");
        }
    }

    // ---------------- compute: warp w owns row w ----------------
    const float* __restrict__ lrow = s_log + warp * 81;
    const float* __restrict__ rrow = s_reg + warp * 405;
    float* __restrict__       orow = s_out + warp * 486;

    // softmax over 81 logits (lanes cover {lane, lane+32, lane+64(<17)})
    const bool  t2 = (lane < 17);
    const float x0 = lrow[lane];
    const float x1 = lrow[lane + 32];
    const float x2 = t2 ? lrow[lane + 64] : -3.402823466e38f;

    float m = fmaxf(fmaxf(x0, x1), x2);
    #pragma unroll
    for (int o = 16; o > 0; o >>= 1)
        m = fmaxf(m, __shfl_xor_sync(0xffffffffu, m, o));

    const float e0 = __expf(x0 - m);
    const float e1 = __expf(x1 - m);
    const float e2 = t2 ? __expf(x2 - m) : 0.0f;

    float s = e0 + e1 + e2;
    #pragma unroll
    for (int o = 16; o > 0; o >>= 1)
        s += __shfl_xor_sync(0xffffffffu, s, o);

    const float inv = __fdividef(1.0f, s);
    orow[lane]      = e0 * inv;
    orow[lane + 32] = e1 * inv;
    if (t2) orow[lane + 64] = e2 * inv;

    // decode: lane owns anchors {lane, lane+32, lane+64(<17)}, 5 floats each
    // (lane*5 mod 32 is a permutation -> conflict-free SMEM access)
    const float CLIP    = 4.135166556742356f;   // log(1000/16)
    const float RAD2DEG = 57.29577951308232f;   // 180/pi

    #pragma unroll
    for (int g = 0; g < 3; ++g) {
        if (g == 2 && !t2) break;
        const int anchor = lane + 32 * g;
        const float* p = rrow + anchor * 5;
        const float a0 = p[0], a1 = p[1], a2 = p[2], a3 = p[3], a4 = p[4];
        float* q = orow + 81 + anchor * 5;
        q[0] = fminf(fmaxf(fmaf(a0 * 0.1f, bw, cx), 0.0f), 1023.0f);
        q[1] = fminf(fmaxf(fmaf(a1 * 0.1f, bh, cy), 0.0f), 1023.0f);
        q[2] = __expf(fminf(a2 * 0.2f, CLIP)) * bw;
        q[3] = __expf(fminf(a3 * 0.2f, CLIP)) * bh;
        q[4] = fmaf(a4, RAD2DEG, ba);
    }

    __syncthreads();   // all s_out writes done before bulk store reads them

    // ---------------- drain output: one bulk store ----------------
    if (tid == 0) {
        asm volatile("fence.proxy.async.shared::cta;" ::: "memory");
        asm volatile(
            "cp.async.bulk.global.shared::cta.bulk_group [%0], [%1], %2;"
            :: "l"(out + (size_t)bid * (PP_RPB * 486)),
               "r"(smem_u32(s_out)), "r"((uint32_t)OUT_B) : "memory");
        asm volatile("cp.async.bulk.commit_group;" ::: "memory");
        asm volatile("cp.async.bulk.wait_group 0;" ::: "memory");
    }
}

extern "C" void kernel_launch(void* const* d_in, const int* in_sizes, int n_in,
                              void* d_out, int out_size)
{
    const float* logits = (const float*)d_in[0];   // [N, 81]
    const float* reg    = (const float*)d_in[1];   // [N, 405]
    const float* boxes  = (const float*)d_in[2];   // [N, 5]
    float*       out    = (float*)d_out;           // [N, 486]

    const int blocks = PP_N / PP_RPB;              // 25000, exact
    PostProcessor_54374285967910_kernel<<<blocks, 256>>>(logits, reg, boxes, out);
}